// round 7
// baseline (speedup 1.0000x reference)
#include <cuda_runtime.h>
#include <cstdint>

#define BB    64
#define SS    1024
#define HH    1000
#define SPLIT 16
#define CHUNK (SS / SPLIT)    /* 64 rows per CTA */
#define WPB   4               /* warps per block */
#define RPW   (CHUNK / WPB)   /* 16 rows per warp */
#define H4    250             /* float4 per row */

#define NGS   16
#define GPS   63

// Scratch (static device arrays: allocation-free per harness rules)
__device__ __align__(16) float g_vp[NGS * BB * HH];     // 4 MB   v partials
__device__ __align__(16) float g_v[BB * HH];            // 256 KB v = h_tgt @ W
__device__ __align__(16) float g_part[SPLIT * BB * HH]; // 4 MB   acc per split
__device__ float g_ml[SPLIT * BB * 2];                  // (m, l) per split
__device__ int   g_cnt_v[16];                           // arrival ctr per h-chunk
__device__ int   g_cnt_a[BB];                           // arrival ctr per batch

// ---------------------------------------------------------------------------
// Kernel 1: v = h_tgt @ W, fused partials + last-CTA reduction.
// grid (16 h-chunks, 16 g-splits), 256 threads. W read once from DRAM.
// Last CTA per h-chunk sums the 16 g-split partials in FIXED order
// (deterministic), then resets the counter for graph replay.
// ---------------------------------------------------------------------------
__global__ __launch_bounds__(256) void v_fused_kernel(
    const float* __restrict__ h_tgt, const float* __restrict__ Wm)
{
    __shared__ float stg[64 * GPS];
    __shared__ int isLast;
    const int hb = blockIdx.x, gs = blockIdx.y;
    const int h0 = hb * 64, g0 = gs * GPS;
    const int gcnt = min(GPS, HH - g0);
    const int t = threadIdx.x;

    for (int idx = t; idx < 64 * GPS; idx += 256) {
        int b  = idx / GPS;
        int gi = idx - b * GPS;
        int g  = g0 + gi;
        stg[idx] = (g < HH) ? h_tgt[b * HH + g] : 0.f;
    }
    __syncthreads();

    const int hq = t & 15, bg = t >> 4;
    const int h  = h0 + hq * 4;
    if ((h + 3) < HH) {
        float4 acc[4];
        #pragma unroll
        for (int i = 0; i < 4; i++) acc[i] = make_float4(0.f, 0.f, 0.f, 0.f);

        #pragma unroll 4
        for (int gi = 0; gi < gcnt; gi++) {
            float4 w4 = __ldg((const float4*)(Wm + (size_t)(g0 + gi) * HH + h));
            #pragma unroll
            for (int bb = 0; bb < 4; bb++) {
                float tb = stg[(bg * 4 + bb) * GPS + gi];
                acc[bb].x += tb * w4.x;
                acc[bb].y += tb * w4.y;
                acc[bb].z += tb * w4.z;
                acc[bb].w += tb * w4.w;
            }
        }
        #pragma unroll
        for (int bb = 0; bb < 4; bb++) {
            int b = bg * 4 + bb;
            *((float4*)(g_vp + (size_t)gs * (BB * HH) + b * HH + h)) = acc[bb];
        }
    }

    // Arrival + last-CTA reduction for this h-chunk
    __threadfence();
    if (t == 0) isLast = (atomicAdd(&g_cnt_v[hb], 1) == NGS - 1);
    __syncthreads();
    if (!isLast) return;
    __threadfence();   // acquire: see all partials

    // Reduce 16 partials: slots = 64 b x 16 float4 (h0..h0+63)
    for (int slot = t; slot < 64 * 16; slot += 256) {
        int b = slot >> 4, k = slot & 15;
        int hh = h0 + 4 * k;
        if (hh + 3 < HH) {
            float4 s = make_float4(0.f, 0.f, 0.f, 0.f);
            #pragma unroll
            for (int g = 0; g < NGS; g++) {
                float4 x = *((const float4*)(g_vp + (size_t)g * (BB * HH) + b * HH + hh));
                s.x += x.x; s.y += x.y; s.z += x.z; s.w += x.w;
            }
            *((float4*)(g_v + (size_t)b * HH + hh)) = s;
        }
    }
    __syncthreads();
    if (t == 0) atomicExch(&g_cnt_v[hb], 0);   // reset for next graph replay
}

// ---------------------------------------------------------------------------
// Kernel 2: warp-autonomous streaming attention + fused in-kernel combine.
// grid (SPLIT, BB) x 128 thr. Each warp: 16 contiguous rows, GMEM->regs
// double-buffered, score+accum from the SAME registers, no mainloop barriers.
// Last split-CTA per batch merges the 16 partials (fixed order) -> output.
// ---------------------------------------------------------------------------
__device__ __forceinline__ void load_row(float4 (&buf)[8],
                                         const float4* __restrict__ p, int lane)
{
    #pragma unroll
    for (int j = 0; j < 7; j++) buf[j] = p[lane + 32 * j];
    buf[7] = make_float4(0.f, 0.f, 0.f, 0.f);
    if (lane < 26) buf[7] = p[224 + lane];
}

__device__ __forceinline__ void process_row(const float4 (&a)[8],
                                            const float4* __restrict__ v4,
                                            int lane, float& m, float& l,
                                            float4 (&acc)[8])
{
    float s0 = 0.f, s1 = 0.f, s2 = 0.f, s3 = 0.f;
    #pragma unroll
    for (int j = 0; j < 7; j++) {
        float4 v = v4[lane + 32 * j];
        s0 += a[j].x * v.x; s1 += a[j].y * v.y;
        s2 += a[j].z * v.z; s3 += a[j].w * v.w;
    }
    if (lane < 26) {
        float4 v = v4[224 + lane];
        s0 += a[7].x * v.x; s1 += a[7].y * v.y;
        s2 += a[7].z * v.z; s3 += a[7].w * v.w;
    }
    float s = (s0 + s1) + (s2 + s3);
    #pragma unroll
    for (int o = 16; o; o >>= 1) s += __shfl_xor_sync(0xffffffffu, s, o);

    float nm   = fmaxf(m, s);
    float corr = __expf(m - nm);
    float p    = __expf(s - nm);
    m = nm;
    l = l * corr + p;
    #pragma unroll
    for (int j = 0; j < 8; j++) {
        acc[j].x = acc[j].x * corr + p * a[j].x;
        acc[j].y = acc[j].y * corr + p * a[j].y;
        acc[j].z = acc[j].z * corr + p * a[j].z;
        acc[j].w = acc[j].w * corr + p * a[j].w;
    }
}

__global__ __launch_bounds__(128) void attn_fused_kernel(
    const float* __restrict__ h_src, float* __restrict__ out)
{
    __shared__ float  sv[1024];          // v for this batch (4 KB)
    __shared__ float4 sacc[WPB][256];    // per-warp acc partials (16 KB)
    __shared__ float  sml[WPB][2];
    __shared__ int    isLast;

    const int sp = blockIdx.x, b = blockIdx.y;
    const int t = threadIdx.x, lane = t & 31, w = t >> 5;

    const float4* rp = (const float4*)(h_src +
        ((size_t)b * SS + (size_t)sp * CHUNK + (size_t)w * RPW) * HH);

    float4 A[8], B[8];
    load_row(A, rp, lane);               // row 0 in flight before sv barrier

    for (int i = t; i < HH; i += 128) sv[i] = g_v[b * HH + i];
    __syncthreads();
    const float4* v4 = (const float4*)sv;

    float m = -1e30f, l = 0.f;
    float4 acc[8];
    #pragma unroll
    for (int j = 0; j < 8; j++) acc[j] = make_float4(0.f, 0.f, 0.f, 0.f);

    #pragma unroll 1
    for (int i = 0; i < RPW; i += 2) {
        load_row(B, rp + H4, lane);                       // row i+1
        process_row(A, v4, lane, m, l, acc);              // row i
        if (i + 2 < RPW) load_row(A, rp + 2 * H4, lane);  // row i+2
        process_row(B, v4, lane, m, l, acc);              // row i+1
        rp += 2 * H4;
    }

    // Merge 4 warp partials within CTA
    #pragma unroll
    for (int j = 0; j < 8; j++) sacc[w][lane + 32 * j] = acc[j];
    if (lane == 0) { sml[w][0] = m; sml[w][1] = l; }
    __syncthreads();

    float M = fmaxf(fmaxf(sml[0][0], sml[1][0]), fmaxf(sml[2][0], sml[3][0]));
    float wgt[WPB];
    float L = 0.f;
    #pragma unroll
    for (int i = 0; i < WPB; i++) {
        wgt[i] = __expf(sml[i][0] - M);
        L += sml[i][1] * wgt[i];
    }

    float4* dst = (float4*)(g_part + (size_t)(sp * BB + b) * HH);
    #pragma unroll
    for (int rep = 0; rep < 2; rep++) {
        int slot = t + rep * 128;
        if (slot < H4) {
            float4 o = make_float4(0.f, 0.f, 0.f, 0.f);
            #pragma unroll
            for (int i = 0; i < WPB; i++) {
                float4 x = sacc[i][slot];
                o.x += wgt[i] * x.x; o.y += wgt[i] * x.y;
                o.z += wgt[i] * x.z; o.w += wgt[i] * x.w;
            }
            dst[slot] = o;
        }
    }
    if (t == 0) {
        g_ml[(sp * BB + b) * 2]     = M;
        g_ml[(sp * BB + b) * 2 + 1] = L;
    }

    // ---- In-kernel combine: last split-CTA of this batch merges all 16 ----
    __threadfence();
    if (t == 0) isLast = (atomicAdd(&g_cnt_a[b], 1) == SPLIT - 1);
    __syncthreads();
    if (!isLast) return;
    __threadfence();   // acquire: see all splits' g_part / g_ml

    float mv[SPLIT], lv[SPLIT];
    #pragma unroll
    for (int i = 0; i < SPLIT; i++) {
        mv[i] = g_ml[(i * BB + b) * 2];
        lv[i] = g_ml[(i * BB + b) * 2 + 1];
    }
    float GM = mv[0];
    #pragma unroll
    for (int i = 1; i < SPLIT; i++) GM = fmaxf(GM, mv[i]);
    float gw[SPLIT];
    float GL = 0.f;
    #pragma unroll
    for (int i = 0; i < SPLIT; i++) { gw[i] = __expf(mv[i] - GM); GL += lv[i] * gw[i]; }
    const float inv = 1.f / GL;

    #pragma unroll
    for (int rep = 0; rep < 2; rep++) {
        int slot = t + rep * 128;
        if (slot < H4) {
            float4 o = make_float4(0.f, 0.f, 0.f, 0.f);
            #pragma unroll
            for (int i = 0; i < SPLIT; i++) {
                float4 x = *((const float4*)(g_part + (size_t)(i * BB + b) * HH) + slot);
                o.x += gw[i] * x.x; o.y += gw[i] * x.y;
                o.z += gw[i] * x.z; o.w += gw[i] * x.w;
            }
            o.x *= inv; o.y *= inv; o.z *= inv; o.w *= inv;
            *((float4*)(out + (size_t)b * HH) + slot) = o;
        }
    }
    __syncthreads();
    if (t == 0) atomicExch(&g_cnt_a[b], 0);   // reset for next graph replay
}

// ---------------------------------------------------------------------------
extern "C" void kernel_launch(void* const* d_in, const int* in_sizes, int n_in,
                              void* d_out, int out_size)
{
    const float* h_tgt = (const float*)d_in[0];   // [64, 1, 1000]
    const float* h_src = (const float*)d_in[1];   // [64, 1024, 1000]
    const float* Wm    = (const float*)d_in[2];   // [1000, 1000]
    // d_in[3] = bias: cancels under softmax shift-invariance; unused.
    float* out = (float*)d_out;                   // [64, 1, 1000]

    v_fused_kernel<<<dim3(16, NGS), 256>>>(h_tgt, Wm);
    attn_fused_kernel<<<dim3(SPLIT, BB), 128>>>(h_src, out);
}

// round 8
// speedup vs baseline: 1.0122x; 1.0122x over previous
#include <cuda_runtime.h>
#include <cstdint>

#define BB    64
#define SS    1024
#define HH    1000
#define SPLIT 16
#define CHUNK (SS / SPLIT)    /* 64 rows per CTA */
#define WPB   4               /* warps per block */
#define RPW   (CHUNK / WPB)   /* 16 rows per warp */
#define H4    250             /* float4 per row */

// Scratch (static device arrays: allocation-free per harness rules)
__device__ __align__(16) float g_v[BB * HH];            // 256 KB v = h_tgt @ W
__device__ __align__(16) float g_part[SPLIT * BB * HH]; // 4 MB   acc per split
__device__ float g_ml[SPLIT * BB * 2];                  // (m, l) per split
__device__ int   g_cnt_a[BB];                           // arrival ctr per batch

__device__ __forceinline__ void cp_async16(void* smem_dst, const void* gmem_src) {
    uint32_t s = (uint32_t)__cvta_generic_to_shared(smem_dst);
    asm volatile("cp.async.cg.shared.global [%0], [%1], 16;\n" :: "r"(s), "l"(gmem_src));
}
#define CP_COMMIT()  asm volatile("cp.async.commit_group;\n" ::: "memory")
#define CP_WAIT(n)   asm volatile("cp.async.wait_group %0;\n" :: "n"(n) : "memory")

// ---------------------------------------------------------------------------
// Kernel 1: v = h_tgt @ W in ONE kernel. grid (16 h-chunks x 8 b-groups).
// Each CTA: 64 h-cols x 8 batches, full K=1000. K split across 16 thread
// groups (r = t>>4), reduced by shfl-pair + fixed-order SMEM tree.
// Deterministic; no global scratch round-trip.
// ---------------------------------------------------------------------------
__global__ __launch_bounds__(256) void v_kernel(
    const float* __restrict__ h_tgt, const float* __restrict__ Wm)
{
    __shared__ __align__(16) float sbuf[8 * HH];   // 32 KB: stg, then reused as red
    const int hb = blockIdx.x;          // h-chunk of 64
    const int bg = blockIdx.y;          // batch group of 8
    const int h0 = hb * 64;
    const int t = threadIdx.x;

    // Stage h_tgt for 8 batches
    for (int i = t; i < 8 * HH; i += 256)
        sbuf[i] = h_tgt[(bg * 8 + i / HH) * HH + (i % HH)];
    __syncthreads();

    const int q = t & 15;               // float4 col within 64-h chunk
    const int r = t >> 4;               // K-split 0..15
    const int h = h0 + q * 4;
    const bool hok = (h + 3) < HH;

    float4 acc[8];
    #pragma unroll
    for (int b = 0; b < 8; b++) acc[b] = make_float4(0.f, 0.f, 0.f, 0.f);

    if (hok) {
        #pragma unroll 8
        for (int g = r; g < HH; g += 16) {
            float4 w4 = __ldg((const float4*)(Wm + (size_t)g * HH + h));
            #pragma unroll
            for (int b = 0; b < 8; b++) {
                float tb = sbuf[b * HH + g];   // warp-broadcast LDS
                acc[b].x += tb * w4.x;
                acc[b].y += tb * w4.y;
                acc[b].z += tb * w4.z;
                acc[b].w += tb * w4.w;
            }
        }
    }

    // Pair-reduce r within warp (lanes 0-15 keep sum of r=2w, 2w+1)
    #pragma unroll
    for (int b = 0; b < 8; b++) {
        acc[b].x += __shfl_down_sync(0xffffffffu, acc[b].x, 16);
        acc[b].y += __shfl_down_sync(0xffffffffu, acc[b].y, 16);
        acc[b].z += __shfl_down_sync(0xffffffffu, acc[b].z, 16);
        acc[b].w += __shfl_down_sync(0xffffffffu, acc[b].w, 16);
    }

    __syncthreads();                    // all stg reads done; reuse sbuf as red
    float4* red = (float4*)sbuf;        // [128 rows][9] (pad col to break conflicts)
    const int w = t >> 5;               // warp id 0..7 (one r-pair per warp)
    if ((t & 31) < 16) {
        #pragma unroll
        for (int b = 0; b < 8; b++)
            red[(q * 8 + b) * 9 + w] = acc[b];
    }
    __syncthreads();

    // Final fixed-order sum of the 8 warp partials -> g_v
    if (t < 128) {
        const int q2 = t >> 3, b2 = t & 7;
        const int h2 = h0 + q2 * 4;
        if (h2 + 3 < HH) {
            float4 s = make_float4(0.f, 0.f, 0.f, 0.f);
            #pragma unroll
            for (int i = 0; i < 8; i++) {
                float4 x = red[(q2 * 8 + b2) * 9 + i];
                s.x += x.x; s.y += x.y; s.z += x.z; s.w += x.w;
            }
            *((float4*)(g_v + (size_t)(bg * 8 + b2) * HH + h2)) = s;
        }
    }
}

// ---------------------------------------------------------------------------
// Kernel 2: warp-autonomous streaming attention + fused combine.
// Row buffers live in per-warp SMEM filled by cp.async (double-buffered):
// regs ~149 -> ~85, 5 CTAs/SM, 20 warps/SM, each warp keeps a 4KB row of
// LDGSTS in flight. No CTA barriers in the mainloop.
// ---------------------------------------------------------------------------
__device__ __forceinline__ void issue_row(float4* dst, const float4* __restrict__ src,
                                          int lane)
{
    #pragma unroll
    for (int j = 0; j < 7; j++) cp_async16(dst + lane + 32 * j, src + lane + 32 * j);
    if (lane < 26) cp_async16(dst + 224 + lane, src + 224 + lane);
}

__device__ __forceinline__ void process_row(const float4* __restrict__ row4,
                                            const float4* __restrict__ v4,
                                            int lane, float& m, float& l,
                                            float4 (&acc)[8])
{
    // Score
    float s0 = 0.f, s1 = 0.f, s2 = 0.f, s3 = 0.f;
    #pragma unroll
    for (int j = 0; j < 7; j++) {
        float4 a = row4[lane + 32 * j];
        float4 v = v4[lane + 32 * j];
        s0 += a.x * v.x; s1 += a.y * v.y;
        s2 += a.z * v.z; s3 += a.w * v.w;
    }
    if (lane < 26) {
        float4 a = row4[224 + lane];
        float4 v = v4[224 + lane];
        s0 += a.x * v.x; s1 += a.y * v.y;
        s2 += a.z * v.z; s3 += a.w * v.w;
    }
    float s = (s0 + s1) + (s2 + s3);
    #pragma unroll
    for (int o = 16; o; o >>= 1) s += __shfl_xor_sync(0xffffffffu, s, o);

    // Online softmax update
    float nm   = fmaxf(m, s);
    float corr = __expf(m - nm);
    float p    = __expf(s - nm);
    m = nm;
    l = l * corr + p;

    // Accumulate (re-read row from SMEM; keeps registers low)
    #pragma unroll
    for (int j = 0; j < 7; j++) {
        float4 a = row4[lane + 32 * j];
        acc[j].x = acc[j].x * corr + p * a.x;
        acc[j].y = acc[j].y * corr + p * a.y;
        acc[j].z = acc[j].z * corr + p * a.z;
        acc[j].w = acc[j].w * corr + p * a.w;
    }
    if (lane < 26) {
        float4 a = row4[224 + lane];
        acc[7].x = acc[7].x * corr + p * a.x;
        acc[7].y = acc[7].y * corr + p * a.y;
        acc[7].z = acc[7].z * corr + p * a.z;
        acc[7].w = acc[7].w * corr + p * a.w;
    } else {
        acc[7].x *= corr; acc[7].y *= corr; acc[7].z *= corr; acc[7].w *= corr;
    }
}

__global__ __launch_bounds__(128, 5) void attn_fused_kernel(
    const float* __restrict__ h_src, float* __restrict__ out)
{
    __shared__ __align__(16) float sv[1024];              // 4 KB
    __shared__ float4 rows[WPB][2][256];                  // 32 KB (reused as sacc)
    __shared__ float  sml[WPB][2];
    __shared__ int    isLast;

    const int sp = blockIdx.x, b = blockIdx.y;
    const int t = threadIdx.x, lane = t & 31, w = t >> 5;

    const float4* rp = (const float4*)(h_src +
        ((size_t)b * SS + (size_t)sp * CHUNK + (size_t)w * RPW) * HH);

    issue_row(rows[w][0], rp, lane);        // row 0 in flight immediately
    CP_COMMIT();

    for (int i = t; i < HH; i += 128) sv[i] = g_v[b * HH + i];
    __syncthreads();
    const float4* v4 = (const float4*)sv;

    float m = -1e30f, l = 0.f;
    float4 acc[8];
    #pragma unroll
    for (int j = 0; j < 8; j++) acc[j] = make_float4(0.f, 0.f, 0.f, 0.f);

    int cur = 0;
    #pragma unroll 1
    for (int i = 0; i < RPW; ++i) {
        if (i + 1 < RPW) {
            issue_row(rows[w][cur ^ 1], rp + H4, lane);
            CP_COMMIT();
            CP_WAIT(1);                     // current row's group complete
        } else {
            CP_WAIT(0);
        }
        __syncwarp();
        process_row(rows[w][cur], v4, lane, m, l, acc);
        cur ^= 1;
        rp += H4;
    }
    __syncwarp();

    // Merge 4 warp partials within CTA (reuse rows[w][0] as sacc[w])
    float4* sacc = rows[w][0];
    #pragma unroll
    for (int j = 0; j < 7; j++) sacc[lane + 32 * j] = acc[j];
    if (lane < 26) sacc[224 + lane] = acc[7];
    if (lane == 0) { sml[w][0] = m; sml[w][1] = l; }
    __syncthreads();

    float M = fmaxf(fmaxf(sml[0][0], sml[1][0]), fmaxf(sml[2][0], sml[3][0]));
    float wgt[WPB];
    float L = 0.f;
    #pragma unroll
    for (int i = 0; i < WPB; i++) {
        wgt[i] = __expf(sml[i][0] - M);
        L += sml[i][1] * wgt[i];
    }

    float4* dst = (float4*)(g_part + (size_t)(sp * BB + b) * HH);
    #pragma unroll
    for (int rep = 0; rep < 2; rep++) {
        int slot = t + rep * 128;
        if (slot < H4) {
            float4 o = make_float4(0.f, 0.f, 0.f, 0.f);
            #pragma unroll
            for (int i = 0; i < WPB; i++) {
                float4 x = rows[i][0][slot];
                o.x += wgt[i] * x.x; o.y += wgt[i] * x.y;
                o.z += wgt[i] * x.z; o.w += wgt[i] * x.w;
            }
            dst[slot] = o;
        }
    }
    if (t == 0) {
        g_ml[(sp * BB + b) * 2]     = M;
        g_ml[(sp * BB + b) * 2 + 1] = L;
    }

    // ---- In-kernel combine: last split-CTA of this batch merges all 16 ----
    __threadfence();
    if (t == 0) isLast = (atomicAdd(&g_cnt_a[b], 1) == SPLIT - 1);
    __syncthreads();
    if (!isLast) return;
    __threadfence();   // acquire: see all splits' g_part / g_ml

    float mv[SPLIT], lv[SPLIT];
    #pragma unroll
    for (int i = 0; i < SPLIT; i++) {
        mv[i] = g_ml[(i * BB + b) * 2];
        lv[i] = g_ml[(i * BB + b) * 2 + 1];
    }
    float GM = mv[0];
    #pragma unroll
    for (int i = 1; i < SPLIT; i++) GM = fmaxf(GM, mv[i]);
    float gw[SPLIT];
    float GL = 0.f;
    #pragma unroll
    for (int i = 0; i < SPLIT; i++) { gw[i] = __expf(mv[i] - GM); GL += lv[i] * gw[i]; }
    const float inv = 1.f / GL;

    #pragma unroll
    for (int rep = 0; rep < 2; rep++) {
        int slot = t + rep * 128;
        if (slot < H4) {
            float4 o = make_float4(0.f, 0.f, 0.f, 0.f);
            #pragma unroll
            for (int i = 0; i < SPLIT; i++) {
                float4 x = *((const float4*)(g_part + (size_t)(i * BB + b) * HH) + slot);
                o.x += gw[i] * x.x; o.y += gw[i] * x.y;
                o.z += gw[i] * x.z; o.w += gw[i] * x.w;
            }
            o.x *= inv; o.y *= inv; o.z *= inv; o.w *= inv;
            *((float4*)(out + (size_t)b * HH) + slot) = o;
        }
    }
    __syncthreads();
    if (t == 0) atomicExch(&g_cnt_a[b], 0);   // reset for next graph replay
}

// ---------------------------------------------------------------------------
extern "C" void kernel_launch(void* const* d_in, const int* in_sizes, int n_in,
                              void* d_out, int out_size)
{
    const float* h_tgt = (const float*)d_in[0];   // [64, 1, 1000]
    const float* h_src = (const float*)d_in[1];   // [64, 1024, 1000]
    const float* Wm    = (const float*)d_in[2];   // [1000, 1000]
    // d_in[3] = bias: cancels under softmax shift-invariance; unused.
    float* out = (float*)d_out;                   // [64, 1, 1000]

    v_kernel<<<dim3(16, 8), 256>>>(h_tgt, Wm);
    attn_fused_kernel<<<dim3(SPLIT, BB), 128>>>(h_src, out);
}

// round 9
// speedup vs baseline: 1.1352x; 1.1216x over previous
#include <cuda_runtime.h>
#include <cstdint>

#define BB    64
#define SS    1024
#define HH    1000
#define SPLIT 32
#define CHUNK (SS / SPLIT)    /* 32 rows per CTA */
#define WPB   4               /* warps per block */
#define RPW   (CHUNK / WPB)   /* 8 rows per warp */
#define H4    250             /* float4 per row */

// Scratch (static device arrays: allocation-free per harness rules)
__device__ __align__(16) float g_v[BB * HH];            // 256 KB v = h_tgt @ W
__device__ __align__(16) float g_part[SPLIT * BB * HH]; // 8 MB   acc per split
__device__ float g_ml[SPLIT * BB * 2];                  // (m, l) per split
__device__ int   g_cnt_a[BB];                           // arrival ctr per batch

// ---------------------------------------------------------------------------
// Kernel 1: v = h_tgt @ W. grid (32 h-chunks x 16 b-groups) = 512 CTAs.
// Each CTA: 32 h-cols x 4 batches, K split over 32 thread-groups,
// reduced via shfl + fixed-order SMEM tree. Deterministic.
// ---------------------------------------------------------------------------
__global__ __launch_bounds__(256) void v_kernel(
    const float* __restrict__ h_tgt, const float* __restrict__ Wm)
{
    __shared__ __align__(16) float sbuf[4 * HH];   // 16 KB: stg, reused as red
    const int hb = blockIdx.x;          // h-chunk of 32 cols
    const int bg = blockIdx.y;          // batch group of 4
    const int h0 = hb * 32;
    const int t = threadIdx.x;

    for (int i = t; i < 4 * HH; i += 256)
        sbuf[i] = h_tgt[(bg * 4 + i / HH) * HH + (i % HH)];
    __syncthreads();

    const int lane = t & 31, w = t >> 5;
    const int q = lane & 7;             // float4 col within chunk
    const int r = (w << 2) + (lane >> 3);   // K-split 0..31
    const int h = h0 + q * 4;
    const bool hok = (h + 3) < HH;

    float4 acc[4];
    #pragma unroll
    for (int b = 0; b < 4; b++) acc[b] = make_float4(0.f, 0.f, 0.f, 0.f);

    if (hok) {
        #pragma unroll 8
        for (int g = r; g < HH; g += 32) {
            float4 w4 = __ldg((const float4*)(Wm + (size_t)g * HH + h));
            #pragma unroll
            for (int b = 0; b < 4; b++) {
                float tb = sbuf[b * HH + g];   // 8-lane broadcast LDS
                acc[b].x += tb * w4.x;
                acc[b].y += tb * w4.y;
                acc[b].z += tb * w4.z;
                acc[b].w += tb * w4.w;
            }
        }
    }

    // Reduce the 4 r-values within each warp: lanes 0-7 end with full sums
    #pragma unroll
    for (int b = 0; b < 4; b++) {
        #pragma unroll
        for (int o = 16; o >= 8; o >>= 1) {
            acc[b].x += __shfl_down_sync(0xffffffffu, acc[b].x, o);
            acc[b].y += __shfl_down_sync(0xffffffffu, acc[b].y, o);
            acc[b].z += __shfl_down_sync(0xffffffffu, acc[b].z, o);
            acc[b].w += __shfl_down_sync(0xffffffffu, acc[b].w, o);
        }
    }

    __syncthreads();                    // stg reads done; reuse sbuf
    float4* red = (float4*)sbuf;        // [32 slots][8 warps]
    if (lane < 8) {
        #pragma unroll
        for (int b = 0; b < 4; b++)
            red[(lane * 4 + b) * 8 + w] = acc[b];
    }
    __syncthreads();

    if (t < 32) {                       // fixed-order final sum -> g_v
        const int q2 = t >> 2, b2 = t & 3;
        const int h2 = h0 + q2 * 4;
        if (h2 + 3 < HH) {
            float4 s = make_float4(0.f, 0.f, 0.f, 0.f);
            #pragma unroll
            for (int i = 0; i < 8; i++) {
                float4 x = red[t * 8 + i];
                s.x += x.x; s.y += x.y; s.z += x.z; s.w += x.w;
            }
            *((float4*)(g_v + (size_t)(bg * 4 + b2) * HH + h2)) = s;
        }
    }
}

// ---------------------------------------------------------------------------
// Kernel 2: warp-autonomous streaming attention (rows in REGISTERS,
// double-buffered LDG) + fused combine. SPLIT=32 -> 2048 small CTAs:
// dynamic backfill tail is halved vs SPLIT=16. Combine epilogue uses
// shfl+SMEM (no register arrays) to keep mainloop register count low.
// ---------------------------------------------------------------------------
__device__ __forceinline__ void load_row(float4 (&buf)[8],
                                         const float4* __restrict__ p, int lane)
{
    #pragma unroll
    for (int j = 0; j < 7; j++) buf[j] = p[lane + 32 * j];
    buf[7] = make_float4(0.f, 0.f, 0.f, 0.f);
    if (lane < 26) buf[7] = p[224 + lane];
}

__device__ __forceinline__ void process_row(const float4 (&a)[8],
                                            const float4* __restrict__ v4,
                                            int lane, float& m, float& l,
                                            float4 (&acc)[8])
{
    float s0 = 0.f, s1 = 0.f, s2 = 0.f, s3 = 0.f;
    #pragma unroll
    for (int j = 0; j < 7; j++) {
        float4 v = v4[lane + 32 * j];
        s0 += a[j].x * v.x; s1 += a[j].y * v.y;
        s2 += a[j].z * v.z; s3 += a[j].w * v.w;
    }
    if (lane < 26) {
        float4 v = v4[224 + lane];
        s0 += a[7].x * v.x; s1 += a[7].y * v.y;
        s2 += a[7].z * v.z; s3 += a[7].w * v.w;
    }
    float s = (s0 + s1) + (s2 + s3);
    #pragma unroll
    for (int o = 16; o; o >>= 1) s += __shfl_xor_sync(0xffffffffu, s, o);

    float nm   = fmaxf(m, s);
    float corr = __expf(m - nm);
    float p    = __expf(s - nm);
    m = nm;
    l = l * corr + p;
    #pragma unroll
    for (int j = 0; j < 8; j++) {
        acc[j].x = acc[j].x * corr + p * a[j].x;
        acc[j].y = acc[j].y * corr + p * a[j].y;
        acc[j].z = acc[j].z * corr + p * a[j].z;
        acc[j].w = acc[j].w * corr + p * a[j].w;
    }
}

__global__ __launch_bounds__(128) void attn_fused_kernel(
    const float* __restrict__ h_src, float* __restrict__ out)
{
    __shared__ __align__(16) float sv[1024];   // 4 KB v
    __shared__ float4 sacc[WPB][256];          // 16 KB warp partials
    __shared__ float  sml[WPB][2];
    __shared__ float  sgw[SPLIT];
    __shared__ float  sInv;
    __shared__ int    isLast;

    const int sp = blockIdx.x, b = blockIdx.y;
    const int t = threadIdx.x, lane = t & 31, w = t >> 5;

    const float4* rp = (const float4*)(h_src +
        ((size_t)b * SS + (size_t)sp * CHUNK + (size_t)w * RPW) * HH);

    float4 A[8], B[8];
    load_row(A, rp, lane);               // row 0 in flight before sv barrier

    for (int i = t; i < HH; i += 128) sv[i] = g_v[b * HH + i];
    __syncthreads();
    const float4* v4 = (const float4*)sv;

    float m = -1e30f, l = 0.f;
    float4 acc[8];
    #pragma unroll
    for (int j = 0; j < 8; j++) acc[j] = make_float4(0.f, 0.f, 0.f, 0.f);

    #pragma unroll 1
    for (int i = 0; i < RPW; i += 2) {
        load_row(B, rp + H4, lane);                       // row i+1
        process_row(A, v4, lane, m, l, acc);              // row i
        if (i + 2 < RPW) load_row(A, rp + 2 * H4, lane);  // row i+2
        process_row(B, v4, lane, m, l, acc);              // row i+1
        rp += 2 * H4;
    }

    // Merge 4 warp partials within CTA
    #pragma unroll
    for (int j = 0; j < 7; j++) sacc[w][lane + 32 * j] = acc[j];
    if (lane < 26) sacc[w][224 + lane] = acc[7];
    if (lane == 0) { sml[w][0] = m; sml[w][1] = l; }
    __syncthreads();

    float M = fmaxf(fmaxf(sml[0][0], sml[1][0]), fmaxf(sml[2][0], sml[3][0]));
    float L = 0.f;
    float wgt[WPB];
    #pragma unroll
    for (int i = 0; i < WPB; i++) {
        wgt[i] = __expf(sml[i][0] - M);
        L += sml[i][1] * wgt[i];
    }

    float4* dst = (float4*)(g_part + (size_t)(sp * BB + b) * HH);
    #pragma unroll
    for (int rep = 0; rep < 2; rep++) {
        int slot = t + rep * 128;
        if (slot < H4) {
            float4 o = make_float4(0.f, 0.f, 0.f, 0.f);
            #pragma unroll
            for (int i = 0; i < WPB; i++) {
                float4 x = sacc[i][slot];
                o.x += wgt[i] * x.x; o.y += wgt[i] * x.y;
                o.z += wgt[i] * x.z; o.w += wgt[i] * x.w;
            }
            dst[slot] = o;
        }
    }
    if (t == 0) {
        g_ml[(sp * BB + b) * 2]     = M;
        g_ml[(sp * BB + b) * 2 + 1] = L;
    }

    // ---- Fused combine: last split-CTA of this batch merges all 32 ----
    __threadfence();
    if (t == 0) isLast = (atomicAdd(&g_cnt_a[b], 1) == SPLIT - 1);
    __syncthreads();
    if (isLast) {
        __threadfence();   // acquire: see all splits' g_part / g_ml

        // Warp 0: lane i owns split i (SPLIT == 32). shfl max + weighted sum.
        if (t < 32) {
            float mi = g_ml[(t * BB + b) * 2];
            float li = g_ml[(t * BB + b) * 2 + 1];
            float GM = mi;
            #pragma unroll
            for (int o = 16; o; o >>= 1)
                GM = fmaxf(GM, __shfl_xor_sync(0xffffffffu, GM, o));
            float gwi  = __expf(mi - GM);
            float term = li * gwi;
            #pragma unroll
            for (int o = 16; o; o >>= 1)
                term += __shfl_xor_sync(0xffffffffu, term, o);
            sgw[t] = gwi;
            if (t == 0) sInv = 1.f / term;
        }
        __syncthreads();

        const float inv = sInv;
        #pragma unroll
        for (int rep = 0; rep < 2; rep++) {
            int slot = t + rep * 128;
            if (slot < H4) {
                float4 o = make_float4(0.f, 0.f, 0.f, 0.f);
                #pragma unroll 8
                for (int i = 0; i < SPLIT; i++) {
                    float4 x = *((const float4*)(g_part + (size_t)(i * BB + b) * HH) + slot);
                    float gwi = sgw[i];
                    o.x += gwi * x.x; o.y += gwi * x.y;
                    o.z += gwi * x.z; o.w += gwi * x.w;
                }
                o.x *= inv; o.y *= inv; o.z *= inv; o.w *= inv;
                *((float4*)(out + (size_t)b * HH) + slot) = o;
            }
        }
        __syncthreads();
        if (t == 0) atomicExch(&g_cnt_a[b], 0);   // reset for graph replay
    }
}

// ---------------------------------------------------------------------------
extern "C" void kernel_launch(void* const* d_in, const int* in_sizes, int n_in,
                              void* d_out, int out_size)
{
    const float* h_tgt = (const float*)d_in[0];   // [64, 1, 1000]
    const float* h_src = (const float*)d_in[1];   // [64, 1024, 1000]
    const float* Wm    = (const float*)d_in[2];   // [1000, 1000]
    // d_in[3] = bias: cancels under softmax shift-invariance; unused.
    float* out = (float*)d_out;                   // [64, 1, 1000]

    v_kernel<<<dim3(32, 16), 256>>>(h_tgt, Wm);
    attn_fused_kernel<<<dim3(SPLIT, BB), 128>>>(h_src, out);
}